// round 6
// baseline (speedup 1.0000x reference)
#include <cuda_runtime.h>
#include <math.h>

// ForestRuthIntegrator — fp32 SIMT v2.1.
// v2 + the missing __syncthreads() before the tid-linear output epilogue
// (final xup writes sx warp-private; epilogue reads it tid-linear -> must barrier).

#define THREADS 512
#define CTA_M   32
#define DDIM    512
#define KDIM    64
#define H2S     34          // sh2t row stride (pad, keeps 8B align)

__device__ __forceinline__ float wrap_torus(float x) {
    const float PI_F     = 3.14159274101257324f;   // float32(pi)
    const float TWO_PI_F = 6.28318548202514648f;   // exactly 2*PI_F
    float t = __fadd_rn(x, PI_F);
    // t in (-2pi, 4pi): single conditional sub/add is bitwise == fmodf path
    if (t >= TWO_PI_F) t = __fsub_rn(t, TWO_PI_F);  // exact (Sterbenz, t<=4pi)
    if (t < 0.0f)      t = __fadd_rn(t, TWO_PI_F);  // mod sign fixup
    return __fsub_rn(t, PI_F);
}

__device__ __forceinline__ void cp16(float* dst_smem, const float* src) {
    unsigned s = (unsigned)__cvta_generic_to_shared(dst_smem);
    asm volatile("cp.async.cg.shared.global [%0], [%1], 16;" :: "r"(s), "l"(src));
}
#define CP_COMMIT() asm volatile("cp.async.commit_group;")
#define CP_WAIT1()  asm volatile("cp.async.wait_group 1;")
#define CP_WAIT0()  asm volatile("cp.async.wait_group 0;")

__global__ __launch_bounds__(THREADS, 1)
void fr_kernel(const float* __restrict__ gx, const float* __restrict__ gv,
               const float* __restrict__ gf, const float* __restrict__ gU,
               const float* __restrict__ gW, const int* __restrict__ gsteps,
               float* __restrict__ gox, float* __restrict__ gov,
               float c1dt, float c2dt, float d1dt, float d2dt)
{
    extern __shared__ float smem[];
    float* sx    = smem;                    // [32][512] 64KB
    float* sv    = sx + CTA_M * DDIM;       // [32][512] 64KB
    float* sh2t  = sv + CTA_M * DDIM;       // [64][H2S] transposed h^2
    float* stage = sh2t + KDIM * H2S;       // 2 x 8192 floats ping-pong, 64KB

    const int tid  = threadIdx.x;
    const int w    = tid >> 5;              // warp 0..15 -> rows 2w, 2w+1
    const int lane = tid & 31;
    const int row0 = blockIdx.x * CTA_M;
    const int r0 = 2 * w, r1 = 2 * w + 1;

    // chunk ids: 0..3 = U rows [128c..128c+128), 4..7 = W cols [128(c-4)..)
    auto issue_chunk = [&](int cid) {
        float* dst = stage + (cid & 1) * 8192;
        if (cid < 4) {
            const float* src = gU + (size_t)cid * 8192;
            #pragma unroll
            for (int i = 0; i < 4; ++i) {
                int idx = tid + i * THREADS;
                cp16(dst + idx * 4, src + idx * 4);
            }
        } else {
            const float* src = gW + (cid - 4) * 128;
            #pragma unroll
            for (int i = 0; i < 4; ++i) {
                int idx = tid + i * THREADS;
                int k = idx >> 5, seg = idx & 31;
                cp16(dst + k * 128 + seg * 4, src + (size_t)k * DDIM + seg * 4);
            }
        }
        CP_COMMIT();
    };

    issue_chunk(0);
    issue_chunk(1);
    {
        const float4* gx4 = (const float4*)(gx + (size_t)row0 * DDIM);
        const float4* gv4 = (const float4*)(gv + (size_t)row0 * DDIM);
        float4* sx4 = (float4*)sx;
        float4* sv4 = (float4*)sv;
        #pragma unroll
        for (int i = 0; i < 8; ++i) {
            sx4[tid + i * THREADS] = gx4[tid + i * THREADS];
            sv4[tid + i * THREADS] = gv4[tid + i * THREADS];
        }
    }
    __syncthreads();

    const int steps = gsteps ? gsteps[0] : 4;

    auto xup = [&](float cdt) {
        #pragma unroll
        for (int i = 0; i < 2; ++i) {
            const int r = 2 * w + i;
            #pragma unroll
            for (int ch = 0; ch < 4; ++ch) {
                const int c = ch * 128 + lane * 4;
                float4 xv = *(float4*)(sx + r * DDIM + c);
                float4 vv = *(const float4*)(sv + r * DDIM + c);
                xv.x = wrap_torus(__fadd_rn(xv.x, __fmul_rn(cdt, vv.x)));
                xv.y = wrap_torus(__fadd_rn(xv.y, __fmul_rn(cdt, vv.y)));
                xv.z = wrap_torus(__fadd_rn(xv.z, __fmul_rn(cdt, vv.z)));
                xv.w = wrap_torus(__fadd_rn(xv.w, __fmul_rn(cdt, vv.w)));
                *(float4*)(sx + r * DDIM + c) = xv;
            }
        }
    };

    auto eval = [&](float ddt) {
        // GEMM1: h[2 rows][2 k] over d, chunked & double-buffered
        float a00 = 0.f, a01 = 0.f, a10 = 0.f, a11 = 0.f;
        const float* svr0 = sv + r0 * DDIM;
        const float* svr1 = sv + r1 * DDIM;
        #pragma unroll 1
        for (int c = 0; c < 4; ++c) {
            CP_WAIT1();
            __syncthreads();
            const float* sU = stage + (c & 1) * 8192;
            const float* p0 = svr0 + c * 128;
            const float* p1 = svr1 + c * 128;
            const float* ub = sU + 2 * lane;
            #pragma unroll 8
            for (int d4 = 0; d4 < 32; ++d4) {
                float4 v0 = *(const float4*)(p0 + d4 * 4);
                float4 v1 = *(const float4*)(p1 + d4 * 4);
                const float* u = ub + (d4 * 4) * KDIM;
                float2 t;
                t = *(const float2*)(u);
                a00 = fmaf(v0.x, t.x, a00); a01 = fmaf(v0.x, t.y, a01);
                a10 = fmaf(v1.x, t.x, a10); a11 = fmaf(v1.x, t.y, a11);
                t = *(const float2*)(u + KDIM);
                a00 = fmaf(v0.y, t.x, a00); a01 = fmaf(v0.y, t.y, a01);
                a10 = fmaf(v1.y, t.x, a10); a11 = fmaf(v1.y, t.y, a11);
                t = *(const float2*)(u + 2 * KDIM);
                a00 = fmaf(v0.z, t.x, a00); a01 = fmaf(v0.z, t.y, a01);
                a10 = fmaf(v1.z, t.x, a10); a11 = fmaf(v1.z, t.y, a11);
                t = *(const float2*)(u + 3 * KDIM);
                a00 = fmaf(v0.w, t.x, a00); a01 = fmaf(v0.w, t.y, a01);
                a10 = fmaf(v1.w, t.x, a10); a11 = fmaf(v1.w, t.y, a11);
            }
            __syncthreads();
            issue_chunk(c + 2);   // 2,3 -> U; then 4,5 -> W0,W1
        }
        // h^2, transposed [k][row] — warp-local columns r0,r1
        sh2t[(2 * lane)     * H2S + r0] = __fmul_rn(a00, a00);
        sh2t[(2 * lane + 1) * H2S + r0] = __fmul_rn(a01, a01);
        sh2t[(2 * lane)     * H2S + r1] = __fmul_rn(a10, a10);
        sh2t[(2 * lane + 1) * H2S + r1] = __fmul_rn(a11, a11);
        __syncwarp();

        // GEMM2: christ[2 rows][4 cols] over k; fused v-update
        #pragma unroll 1
        for (int c = 0; c < 4; ++c) {
            CP_WAIT1();
            __syncthreads();
            const float* sW = stage + (c & 1) * 8192;
            const int col = c * 128 + lane * 4;
            const float4 f0 = *(const float4*)(gf + (size_t)(row0 + r0) * DDIM + col);
            const float4 f1 = *(const float4*)(gf + (size_t)(row0 + r1) * DDIM + col);
            float b00 = 0.f, b01 = 0.f, b02 = 0.f, b03 = 0.f;
            float b10 = 0.f, b11 = 0.f, b12 = 0.f, b13 = 0.f;
            const float* wb = sW + lane * 4;
            const float* hb = sh2t + r0;
            #pragma unroll 8
            for (int k = 0; k < KDIM; ++k) {
                float4 wv = *(const float4*)(wb + k * 128);
                float2 hh = *(const float2*)(hb + k * H2S);
                b00 = fmaf(hh.x, wv.x, b00); b01 = fmaf(hh.x, wv.y, b01);
                b02 = fmaf(hh.x, wv.z, b02); b03 = fmaf(hh.x, wv.w, b03);
                b10 = fmaf(hh.y, wv.x, b10); b11 = fmaf(hh.y, wv.y, b11);
                b12 = fmaf(hh.y, wv.z, b12); b13 = fmaf(hh.y, wv.w, b13);
            }
            float4 vv0 = *(float4*)(sv + r0 * DDIM + col);
            vv0.x = __fadd_rn(vv0.x, __fmul_rn(ddt, __fadd_rn(-b00, f0.x)));
            vv0.y = __fadd_rn(vv0.y, __fmul_rn(ddt, __fadd_rn(-b01, f0.y)));
            vv0.z = __fadd_rn(vv0.z, __fmul_rn(ddt, __fadd_rn(-b02, f0.z)));
            vv0.w = __fadd_rn(vv0.w, __fmul_rn(ddt, __fadd_rn(-b03, f0.w)));
            *(float4*)(sv + r0 * DDIM + col) = vv0;
            float4 vv1 = *(float4*)(sv + r1 * DDIM + col);
            vv1.x = __fadd_rn(vv1.x, __fmul_rn(ddt, __fadd_rn(-b10, f1.x)));
            vv1.y = __fadd_rn(vv1.y, __fmul_rn(ddt, __fadd_rn(-b11, f1.y)));
            vv1.z = __fadd_rn(vv1.z, __fmul_rn(ddt, __fadd_rn(-b12, f1.z)));
            vv1.w = __fadd_rn(vv1.w, __fmul_rn(ddt, __fadd_rn(-b13, f1.w)));
            *(float4*)(sv + r1 * DDIM + col) = vv1;
            __syncthreads();
            issue_chunk((c + 6) & 7);   // 6,7 -> W2,W3; then 0,1 -> next eval's U
        }
    };

    for (int s = 0; s < steps; ++s) {
        xup(c1dt);
        eval(d1dt);
        xup(c2dt);
        eval(d2dt);
        xup(c2dt);   // C3 == C2
        eval(d1dt);  // D3 == D1
        xup(c1dt);   // C4 == C1
    }

    // Epilogue is tid-linear across the whole tile -> MUST barrier after the
    // warp-private final xup. (This was the round-2 bug.)
    __syncthreads();
    {
        float4* gox4 = (float4*)(gox + (size_t)row0 * DDIM);
        float4* gov4 = (float4*)(gov + (size_t)row0 * DDIM);
        const float4* sx4 = (const float4*)sx;
        const float4* sv4 = (const float4*)sv;
        #pragma unroll
        for (int i = 0; i < 8; ++i) {
            gox4[tid + i * THREADS] = sx4[tid + i * THREADS];
            gov4[tid + i * THREADS] = sv4[tid + i * THREADS];
        }
    }
    CP_WAIT0();   // drain dangling prefetch groups before exit
}

extern "C" void kernel_launch(void* const* d_in, const int* in_sizes, int n_in,
                              void* d_out, int out_size)
{
    const float* x = (const float*)d_in[0];
    const float* v = (const float*)d_in[1];
    const float* f = (const float*)d_in[2];
    const float* U = (const float*)d_in[3];
    const float* W = (const float*)d_in[4];
    const int* steps = (n_in >= 6) ? (const int*)d_in[5] : nullptr;

    const int B  = in_sizes[0] / DDIM;
    const int BD = B * DDIM;
    float* ox = (float*)d_out;
    float* ov = ox + BD;

    const double theta = 1.0 / (2.0 - pow(2.0, 1.0 / 3.0));
    const float c1dt = (float)((theta / 2.0) * 0.01);
    const float c2dt = (float)(((1.0 - theta) / 2.0) * 0.01);
    const float d1dt = (float)(theta * 0.01);
    const float d2dt = (float)((1.0 - 2.0 * theta) * 0.01);

    const int smem_bytes = (2 * CTA_M * DDIM + KDIM * H2S + 2 * 8192) * 4;  // 205,312 B
    cudaFuncSetAttribute(fr_kernel, cudaFuncAttributeMaxDynamicSharedMemorySize, smem_bytes);
    fr_kernel<<<B / CTA_M, THREADS, smem_bytes>>>(x, v, f, U, W, steps, ox, ov,
                                                  c1dt, c2dt, d1dt, d2dt);
}

// round 7
// speedup vs baseline: 2.0966x; 2.0966x over previous
#include <cuda_runtime.h>
#include <math.h>

// ForestRuthIntegrator v3 — v-autonomous h-recurrence.
// h = v@U evolves by h' = h + ddt*(-(h*h)@WU + fU), WU=W@U (pre-kernel),
// fU=force@U (prologue, fused with h0 = v@U). Per-eval work = GEMM2 only:
// christ = (h*h)@W with 8-row x 4-col warp tiles, 2-way k-split.
// x in registers, v in smem, W streamed by cp.async.

#define THREADS 512
#define CTA_M   32
#define DDIM    512
#define KDIM    64
#define H2S     36     // h^2-transposed row stride (pad), 144B = 16B-aligned
#define WUS     66     // WU row stride (pad)

__device__ float g_WU[KDIM * KDIM];

__global__ void wu_kernel(const float* __restrict__ gW, const float* __restrict__ gU) {
    int idx = blockIdx.x * blockDim.x + threadIdx.x;   // 4096 threads
    int a = idx >> 6, b = idx & 63;
    float s = 0.f;
    #pragma unroll 8
    for (int d = 0; d < DDIM; ++d)
        s = fmaf(gW[a * DDIM + d], gU[d * KDIM + b], s);
    g_WU[a * KDIM + b] = s;
}

__device__ __forceinline__ float wrap_torus(float x) {
    const float PI_F     = 3.14159274101257324f;
    const float TWO_PI_F = 6.28318548202514648f;
    float t = __fadd_rn(x, PI_F);
    if (t >= TWO_PI_F) t = __fsub_rn(t, TWO_PI_F);  // exact (Sterbenz, t<4pi)
    if (t < 0.0f)      t = __fadd_rn(t, TWO_PI_F);
    return __fsub_rn(t, PI_F);
}

__device__ __forceinline__ void cp16(float* dst_smem, const float* src) {
    unsigned s = (unsigned)__cvta_generic_to_shared(dst_smem);
    asm volatile("cp.async.cg.shared.global [%0], [%1], 16;" :: "r"(s), "l"(src));
}
#define CP_COMMIT() asm volatile("cp.async.commit_group;")
#define CP_WAIT1()  asm volatile("cp.async.wait_group 1;")
#define CP_WAIT0()  asm volatile("cp.async.wait_group 0;")

__global__ __launch_bounds__(THREADS, 1)
void fr_kernel(const float* __restrict__ gx, const float* __restrict__ gv,
               const float* __restrict__ gf, const float* __restrict__ gU,
               const float* __restrict__ gW, const int* __restrict__ gsteps,
               float* __restrict__ gox, float* __restrict__ gov,
               float c1dt, float c2dt, float d1dt, float d2dt)
{
    extern __shared__ float smem[];
    float* sv    = smem;                       // [32][512]      64 KB
    float* sh    = sv    + CTA_M * DDIM;       // h  [32][64]     8 KB
    float* sfU   = sh    + CTA_M * KDIM;       // fU [32][64]     8 KB
    float* h2t   = sfU   + CTA_M * KDIM;       // 2x [64][H2S]   18 KB (h^2 transposed, dbl-buf)
    float* sWU   = h2t   + 2 * KDIM * H2S;     // [64][WUS]     16.5 KB
    float* spart = sWU   + KDIM * WUS;         // 8192 f         32 KB (partials scratch)
    float* stage = spart + 8192;               // 2 x 8192 f     64 KB (cp.async ping-pong)

    const int tid  = threadIdx.x;
    const int wid  = tid >> 5;
    const int lane = tid & 31;
    const int row0 = blockIdx.x * CTA_M;
    const int g  = wid >> 2;          // row-group: rows 8g..8g+7
    const int cc = (wid >> 1) & 1;    // chunk-within-phase
    const int ks = wid & 1;           // k-half (GEMM2)
    const int ms = wid & 3;           // kin-slice (mini-GEMM)

    auto issueU = [&](int c) {        // U chunk c (128 d-rows) -> stage[c&1]
        float* dst = stage + (c & 1) * 8192;
        const float* src = gU + (size_t)c * 8192;
        #pragma unroll
        for (int i = 0; i < 4; ++i) { int idx = tid + i * THREADS; cp16(dst + idx * 4, src + idx * 4); }
        CP_COMMIT();
    };
    auto issueW = [&](int c) {        // W col-chunk c (128 cols) -> stage[c&1], layout [64][128]
        float* dst = stage + (c & 1) * 8192;
        const float* src = gW + c * 128;
        #pragma unroll
        for (int i = 0; i < 4; ++i) {
            int idx = tid + i * THREADS;
            int k = idx >> 5, seg = idx & 31;
            cp16(dst + k * 128 + seg * 4, src + (size_t)k * DDIM + seg * 4);
        }
        CP_COMMIT();
    };

    issueU(0); issueU(1);

    float4 xr[8];                     // x register-resident, tid-linear float4 tiling
    {
        const float4* gx4 = (const float4*)(gx + (size_t)row0 * DDIM);
        const float4* gv4 = (const float4*)(gv + (size_t)row0 * DDIM);
        float4* sv4 = (float4*)sv;
        #pragma unroll
        for (int i = 0; i < 8; ++i) {
            xr[i] = gx4[tid + i * THREADS];
            sv4[tid + i * THREADS] = gv4[tid + i * THREADS];
        }
        #pragma unroll
        for (int i = 0; i < 8; ++i) {
            int idx = tid + i * THREADS;               // 4096 WU elements
            sWU[(idx >> 6) * WUS + (idx & 63)] = g_WU[idx];
        }
    }
    __syncthreads();

    const int steps = gsteps ? gsteps[0] : 4;

    // ---- prologue: h0 = v@U and fU = force@U (fused; 2 rows/warp, 2 kout/lane) ----
    {
        float ah00=0.f, ah01=0.f, ah10=0.f, ah11=0.f;
        float af00=0.f, af01=0.f, af10=0.f, af11=0.f;
        const int pr0 = 2 * wid, pr1 = 2 * wid + 1;
        #pragma unroll 1
        for (int c = 0; c < 4; ++c) {
            CP_WAIT1(); __syncthreads();
            const float* sU = stage + (c & 1) * 8192;
            const float* p0 = sv + pr0 * DDIM + c * 128;
            const float* p1 = sv + pr1 * DDIM + c * 128;
            const float* q0 = gf + (size_t)(row0 + pr0) * DDIM + c * 128;
            const float* q1 = gf + (size_t)(row0 + pr1) * DDIM + c * 128;
            const float* ub = sU + 2 * lane;
            #pragma unroll 4
            for (int d4 = 0; d4 < 32; ++d4) {
                float4 v0 = *(const float4*)(p0 + d4 * 4);
                float4 v1 = *(const float4*)(p1 + d4 * 4);
                float4 f0 = *(const float4*)(q0 + d4 * 4);
                float4 f1 = *(const float4*)(q1 + d4 * 4);
                const float* u = ub + (d4 * 4) * KDIM;
                float2 t;
                t = *(const float2*)(u);
                ah00 = fmaf(v0.x, t.x, ah00); ah01 = fmaf(v0.x, t.y, ah01);
                ah10 = fmaf(v1.x, t.x, ah10); ah11 = fmaf(v1.x, t.y, ah11);
                af00 = fmaf(f0.x, t.x, af00); af01 = fmaf(f0.x, t.y, af01);
                af10 = fmaf(f1.x, t.x, af10); af11 = fmaf(f1.x, t.y, af11);
                t = *(const float2*)(u + KDIM);
                ah00 = fmaf(v0.y, t.x, ah00); ah01 = fmaf(v0.y, t.y, ah01);
                ah10 = fmaf(v1.y, t.x, ah10); ah11 = fmaf(v1.y, t.y, ah11);
                af00 = fmaf(f0.y, t.x, af00); af01 = fmaf(f0.y, t.y, af01);
                af10 = fmaf(f1.y, t.x, af10); af11 = fmaf(f1.y, t.y, af11);
                t = *(const float2*)(u + 2 * KDIM);
                ah00 = fmaf(v0.z, t.x, ah00); ah01 = fmaf(v0.z, t.y, ah01);
                ah10 = fmaf(v1.z, t.x, ah10); ah11 = fmaf(v1.z, t.y, ah11);
                af00 = fmaf(f0.z, t.x, af00); af01 = fmaf(f0.z, t.y, af01);
                af10 = fmaf(f1.z, t.x, af10); af11 = fmaf(f1.z, t.y, af11);
                t = *(const float2*)(u + 3 * KDIM);
                ah00 = fmaf(v0.w, t.x, ah00); ah01 = fmaf(v0.w, t.y, ah01);
                ah10 = fmaf(v1.w, t.x, ah10); ah11 = fmaf(v1.w, t.y, ah11);
                af00 = fmaf(f0.w, t.x, af00); af01 = fmaf(f0.w, t.y, af01);
                af10 = fmaf(f1.w, t.x, af10); af11 = fmaf(f1.w, t.y, af11);
            }
            __syncthreads();
            if (c < 2) issueU(c + 2);
            else       issueW(c - 2);   // W0, W1 for eval 0 phase 0
        }
        sh[pr0 * KDIM + 2 * lane] = ah00;  sh[pr0 * KDIM + 2 * lane + 1] = ah01;
        sh[pr1 * KDIM + 2 * lane] = ah10;  sh[pr1 * KDIM + 2 * lane + 1] = ah11;
        sfU[pr0 * KDIM + 2 * lane] = af00; sfU[pr0 * KDIM + 2 * lane + 1] = af01;
        sfU[pr1 * KDIM + 2 * lane] = af10; sfU[pr1 * KDIM + 2 * lane + 1] = af11;
        h2t[(2 * lane)     * H2S + pr0] = __fmul_rn(ah00, ah00);
        h2t[(2 * lane + 1) * H2S + pr0] = __fmul_rn(ah01, ah01);
        h2t[(2 * lane)     * H2S + pr1] = __fmul_rn(ah10, ah10);
        h2t[(2 * lane + 1) * H2S + pr1] = __fmul_rn(ah11, ah11);
    }
    __syncthreads();

    int epar = 0;

    auto evalstep = [&](float ddt) {
        const float* h2r = h2t + epar * KDIM * H2S;
        float* h2w = h2t + (epar ^ 1) * KDIM * H2S;

        // ---- GEMM2: christ = h^2 @ W ; warp=(g,cc,ks): 8 rows, 128 cols, 32 k ----
        #pragma unroll 1
        for (int P = 0; P < 2; ++P) {
            CP_WAIT0(); __syncthreads();
            const float* sWc = stage + cc * 8192;      // chunk 2P+cc lives in stage[cc]
            float4 A[8];
            #pragma unroll
            for (int i = 0; i < 8; ++i) A[i] = make_float4(0.f, 0.f, 0.f, 0.f);
            const float* wb = sWc + lane * 4 + ks * 32 * 128;
            const float* hb = h2r + 8 * g + ks * 32 * H2S;
            #pragma unroll 8
            for (int k = 0; k < 32; ++k) {
                float4 wv = *(const float4*)(wb + k * 128);
                float4 hA = *(const float4*)(hb + k * H2S);
                float4 hB = *(const float4*)(hb + k * H2S + 4);
                A[0].x = fmaf(hA.x, wv.x, A[0].x); A[0].y = fmaf(hA.x, wv.y, A[0].y);
                A[0].z = fmaf(hA.x, wv.z, A[0].z); A[0].w = fmaf(hA.x, wv.w, A[0].w);
                A[1].x = fmaf(hA.y, wv.x, A[1].x); A[1].y = fmaf(hA.y, wv.y, A[1].y);
                A[1].z = fmaf(hA.y, wv.z, A[1].z); A[1].w = fmaf(hA.y, wv.w, A[1].w);
                A[2].x = fmaf(hA.z, wv.x, A[2].x); A[2].y = fmaf(hA.z, wv.y, A[2].y);
                A[2].z = fmaf(hA.z, wv.z, A[2].z); A[2].w = fmaf(hA.z, wv.w, A[2].w);
                A[3].x = fmaf(hA.w, wv.x, A[3].x); A[3].y = fmaf(hA.w, wv.y, A[3].y);
                A[3].z = fmaf(hA.w, wv.z, A[3].z); A[3].w = fmaf(hA.w, wv.w, A[3].w);
                A[4].x = fmaf(hB.x, wv.x, A[4].x); A[4].y = fmaf(hB.x, wv.y, A[4].y);
                A[4].z = fmaf(hB.x, wv.z, A[4].z); A[4].w = fmaf(hB.x, wv.w, A[4].w);
                A[5].x = fmaf(hB.y, wv.x, A[5].x); A[5].y = fmaf(hB.y, wv.y, A[5].y);
                A[5].z = fmaf(hB.y, wv.z, A[5].z); A[5].w = fmaf(hB.y, wv.w, A[5].w);
                A[6].x = fmaf(hB.z, wv.x, A[6].x); A[6].y = fmaf(hB.z, wv.y, A[6].y);
                A[6].z = fmaf(hB.z, wv.z, A[6].z); A[6].w = fmaf(hB.z, wv.w, A[6].w);
                A[7].x = fmaf(hB.w, wv.x, A[7].x); A[7].y = fmaf(hB.w, wv.y, A[7].y);
                A[7].z = fmaf(hB.w, wv.z, A[7].z); A[7].w = fmaf(hB.w, wv.w, A[7].w);
            }
            if (ks == 1) {                              // publish upper-k partial
                float* dp = spart + (g * 2 + cc) * 1024 + lane * 4;
                #pragma unroll
                for (int i = 0; i < 8; ++i) *(float4*)(dp + i * 128) = A[i];
            }
            __syncthreads();
            if (P == 0) { issueW(2); issueW(3); }       // mid-eval prefetch
            else        { issueW(0); issueW(1); }       // next eval's phase-0 chunks
            if (ks == 0) {                              // merge + v-update
                const int chunk = 2 * P + cc;
                const int col = chunk * 128 + lane * 4;
                const float* sp = spart + (g * 2 + cc) * 1024 + lane * 4;
                #pragma unroll
                for (int i = 0; i < 8; ++i) {
                    float4 p = *(const float4*)(sp + i * 128);
                    float cx = __fadd_rn(A[i].x, p.x);
                    float cy = __fadd_rn(A[i].y, p.y);
                    float cz = __fadd_rn(A[i].z, p.z);
                    float cw = __fadd_rn(A[i].w, p.w);
                    float4 fv = *(const float4*)(gf + (size_t)(row0 + 8 * g + i) * DDIM + col);
                    float* vp = sv + (8 * g + i) * DDIM + col;
                    float4 vv = *(float4*)vp;
                    vv.x = __fadd_rn(vv.x, __fmul_rn(ddt, __fadd_rn(-cx, fv.x)));
                    vv.y = __fadd_rn(vv.y, __fmul_rn(ddt, __fadd_rn(-cy, fv.y)));
                    vv.z = __fadd_rn(vv.z, __fmul_rn(ddt, __fadd_rn(-cz, fv.z)));
                    vv.w = __fadd_rn(vv.w, __fmul_rn(ddt, __fadd_rn(-cw, fv.w)));
                    *(float4*)vp = vv;
                }
            }
        }
        __syncthreads();   // spart free for mini-GEMM reuse

        // ---- mini-GEMM: h' = h + ddt*(-(h^2 @ WU) + fU) ; warp=(g,ms): 16 kin ----
        {
            const float* h2b = h2r + 8 * g;
            const float* wub = sWU + 2 * lane;
            float p0[8], p1[8];
            #pragma unroll
            for (int i = 0; i < 8; ++i) { p0[i] = 0.f; p1[i] = 0.f; }
            #pragma unroll 4
            for (int t = 0; t < 16; ++t) {
                int kin = ms * 16 + t;
                float2 wu = *(const float2*)(wub + kin * WUS);
                float4 hA = *(const float4*)(h2b + kin * H2S);
                float4 hB = *(const float4*)(h2b + kin * H2S + 4);
                p0[0] = fmaf(hA.x, wu.x, p0[0]); p1[0] = fmaf(hA.x, wu.y, p1[0]);
                p0[1] = fmaf(hA.y, wu.x, p0[1]); p1[1] = fmaf(hA.y, wu.y, p1[1]);
                p0[2] = fmaf(hA.z, wu.x, p0[2]); p1[2] = fmaf(hA.z, wu.y, p1[2]);
                p0[3] = fmaf(hA.w, wu.x, p0[3]); p1[3] = fmaf(hA.w, wu.y, p1[3]);
                p0[4] = fmaf(hB.x, wu.x, p0[4]); p1[4] = fmaf(hB.x, wu.y, p1[4]);
                p0[5] = fmaf(hB.y, wu.x, p0[5]); p1[5] = fmaf(hB.y, wu.y, p1[5]);
                p0[6] = fmaf(hB.z, wu.x, p0[6]); p1[6] = fmaf(hB.z, wu.y, p1[6]);
                p0[7] = fmaf(hB.w, wu.x, p0[7]); p1[7] = fmaf(hB.w, wu.y, p1[7]);
            }
            float* dp = spart + wid * 512 + 2 * lane;
            #pragma unroll
            for (int i = 0; i < 8; ++i) *(float2*)(dp + i * 64) = make_float2(p0[i], p1[i]);
        }
        __syncthreads();
        if (ms == 0) {                                  // reduce 4 kin-slices, update h
            #pragma unroll
            for (int i = 0; i < 8; ++i) {
                const int r = 8 * g + i;
                float2 s0 = *(const float2*)(spart + (4 * g + 0) * 512 + i * 64 + 2 * lane);
                float2 s1 = *(const float2*)(spart + (4 * g + 1) * 512 + i * 64 + 2 * lane);
                float2 s2 = *(const float2*)(spart + (4 * g + 2) * 512 + i * 64 + 2 * lane);
                float2 s3 = *(const float2*)(spart + (4 * g + 3) * 512 + i * 64 + 2 * lane);
                float sx = __fadd_rn(__fadd_rn(s0.x, s1.x), __fadd_rn(s2.x, s3.x));
                float sy = __fadd_rn(__fadd_rn(s0.y, s1.y), __fadd_rn(s2.y, s3.y));
                float2 hv = *(const float2*)(sh  + r * KDIM + 2 * lane);
                float2 fv = *(const float2*)(sfU + r * KDIM + 2 * lane);
                float hnx = __fadd_rn(hv.x, __fmul_rn(ddt, __fadd_rn(-sx, fv.x)));
                float hny = __fadd_rn(hv.y, __fmul_rn(ddt, __fadd_rn(-sy, fv.y)));
                *(float2*)(sh + r * KDIM + 2 * lane) = make_float2(hnx, hny);
                h2w[(2 * lane)     * H2S + r] = __fmul_rn(hnx, hnx);
                h2w[(2 * lane + 1) * H2S + r] = __fmul_rn(hny, hny);
            }
        }
        __syncthreads();
        epar ^= 1;
    };

    auto xup = [&](float cdt) {
        const float4* sv4 = (const float4*)sv;
        #pragma unroll
        for (int i = 0; i < 8; ++i) {
            float4 vv = sv4[tid + i * THREADS];
            xr[i].x = wrap_torus(__fadd_rn(xr[i].x, __fmul_rn(cdt, vv.x)));
            xr[i].y = wrap_torus(__fadd_rn(xr[i].y, __fmul_rn(cdt, vv.y)));
            xr[i].z = wrap_torus(__fadd_rn(xr[i].z, __fmul_rn(cdt, vv.z)));
            xr[i].w = wrap_torus(__fadd_rn(xr[i].w, __fmul_rn(cdt, vv.w)));
        }
    };

    for (int s = 0; s < steps; ++s) {
        xup(c1dt);
        evalstep(d1dt);
        xup(c2dt);
        evalstep(d2dt);
        xup(c2dt);     // C3 == C2
        evalstep(d1dt); // D3 == D1
        xup(c1dt);     // C4 == C1
    }

    {
        float4* gox4 = (float4*)(gox + (size_t)row0 * DDIM);
        float4* gov4 = (float4*)(gov + (size_t)row0 * DDIM);
        const float4* sv4 = (const float4*)sv;
        #pragma unroll
        for (int i = 0; i < 8; ++i) {
            gox4[tid + i * THREADS] = xr[i];
            gov4[tid + i * THREADS] = sv4[tid + i * THREADS];
        }
    }
    CP_WAIT0();   // drain dangling prefetch groups
}

extern "C" void kernel_launch(void* const* d_in, const int* in_sizes, int n_in,
                              void* d_out, int out_size)
{
    const float* x = (const float*)d_in[0];
    const float* v = (const float*)d_in[1];
    const float* f = (const float*)d_in[2];
    const float* U = (const float*)d_in[3];
    const float* W = (const float*)d_in[4];
    const int* steps = (n_in >= 6) ? (const int*)d_in[5] : nullptr;

    const int B  = in_sizes[0] / DDIM;
    const int BD = B * DDIM;
    float* ox = (float*)d_out;
    float* ov = ox + BD;

    const double theta = 1.0 / (2.0 - pow(2.0, 1.0 / 3.0));
    const float c1dt = (float)((theta / 2.0) * 0.01);
    const float c2dt = (float)(((1.0 - theta) / 2.0) * 0.01);
    const float d1dt = (float)(theta * 0.01);
    const float d2dt = (float)((1.0 - 2.0 * theta) * 0.01);

    wu_kernel<<<16, 256>>>(W, U);

    const int smem_floats = CTA_M * DDIM + 2 * CTA_M * KDIM + 2 * KDIM * H2S
                          + KDIM * WUS + 8192 + 2 * 8192;      // 53888
    const int smem_bytes = smem_floats * 4;                    // 215,552 B
    cudaFuncSetAttribute(fr_kernel, cudaFuncAttributeMaxDynamicSharedMemorySize, smem_bytes);
    fr_kernel<<<B / CTA_M, THREADS, smem_bytes>>>(x, v, f, U, W, steps, ox, ov,
                                                  c1dt, c2dt, d1dt, d2dt);
}

// round 8
// speedup vs baseline: 3.6382x; 1.7353x over previous
#include <cuda_runtime.h>
#include <math.h>

// ForestRuthIntegrator v4 — fully K-space trajectory.
// h' = h + ddt*(-(h*h)@WU + fU); S_v += delta*h^2, S_x += delta*gamma*h^2 (regs).
// Epilogue: Gv=S_v@W, Gx=S_x@W fused; v = v0 + dt*(-Gv + steps*f);
// x = wrap(x0 + steps*dt*v0 + dt^2*(-Gx + Gamma*f)).

#define THREADS 512
#define CTA_M   32
#define DDIM    512
#define KDIM    64
#define WUS     68      // WU row stride (16B-aligned)
#define H2SS    68      // eval h^2 row stride
#define STS_    36      // epilogue transposed-S stride

__device__ float g_WU[KDIM * KDIM];

__global__ void wu_kernel(const float* __restrict__ gW, const float* __restrict__ gU) {
    int idx = blockIdx.x * blockDim.x + threadIdx.x;   // 4096 threads
    int a = idx >> 6, b = idx & 63;
    float s = 0.f;
    #pragma unroll 8
    for (int d = 0; d < DDIM; ++d)
        s = fmaf(gW[a * DDIM + d], gU[d * KDIM + b], s);
    g_WU[a * KDIM + b] = s;
}

__device__ __forceinline__ float wrap_torus(float x) {
    const float PI_F     = 3.14159274101257324f;
    const float TWO_PI_F = 6.28318548202514648f;
    float t = __fadd_rn(x, PI_F);
    if (t >= TWO_PI_F) t = __fsub_rn(t, TWO_PI_F);  // exact (Sterbenz, t<4pi)
    if (t < 0.0f)      t = __fadd_rn(t, TWO_PI_F);
    return __fsub_rn(t, PI_F);
}

__device__ __forceinline__ void cp16(float* dst_smem, const float* src) {
    unsigned s = (unsigned)__cvta_generic_to_shared(dst_smem);
    asm volatile("cp.async.cg.shared.global [%0], [%1], 16;" :: "r"(s), "l"(src));
}
#define CP_COMMIT() asm volatile("cp.async.commit_group;")
#define CP_WAIT1()  asm volatile("cp.async.wait_group 1;")
#define CP_WAIT0()  asm volatile("cp.async.wait_group 0;")

__global__ __launch_bounds__(THREADS, 1)
void fr_kernel(const float* __restrict__ gx, const float* __restrict__ gv,
               const float* __restrict__ gf, const float* __restrict__ gU,
               const float* __restrict__ gW, const int* __restrict__ gsteps,
               float* __restrict__ gox, float* __restrict__ gov)
{
    extern __shared__ float smem[];
    float* sv    = smem;                 // [32][512]           16384 f
    float* sh    = sv    + 16384;        // h0   [32][64]        2048 f
    float* sfU   = sh    + 2048;         // fU   [32][64]        2048 f
    float* kbuf  = sfU   + 2048;         // evals: 2x[32][68]; epi: 2x[64][36]  4608 f
    float* sWU   = kbuf  + 4608;         // [64][WUS]            4352 f
    float* spart = sWU   + 4352;         // merge scratch        8192 f
    float* stage = spart + 8192;         // cp.async ping-pong  16384 f

    const int tid  = threadIdx.x;
    const int wid  = tid >> 5;
    const int lane = tid & 31;
    const int row0 = blockIdx.x * CTA_M;
    // eval-phase thread ownership: row er, cols ec..ec+3 of [32][64]
    const int er = tid >> 4;
    const int ec = (tid & 15) * 4;
    // epilogue warp roles
    const int g  = wid >> 2;            // rows 8g..8g+7
    const int cc = (wid >> 1) & 1;      // chunk parity
    const int ks = wid & 1;             // k-half

    auto issueU = [&](int c) {
        float* dst = stage + (c & 1) * 8192;
        const float* src = gU + (size_t)c * 8192;
        #pragma unroll
        for (int i = 0; i < 4; ++i) { int idx = tid + i * THREADS; cp16(dst + idx * 4, src + idx * 4); }
        CP_COMMIT();
    };
    auto issueW = [&](int c) {          // W col-chunk c -> stage[c&1], layout [64][128]
        float* dst = stage + (c & 1) * 8192;
        const float* src = gW + c * 128;
        #pragma unroll
        for (int i = 0; i < 4; ++i) {
            int idx = tid + i * THREADS;
            int k = idx >> 5, seg = idx & 31;
            cp16(dst + k * 128 + seg * 4, src + (size_t)k * DDIM + seg * 4);
        }
        CP_COMMIT();
    };

    issueU(0); issueU(1);
    {
        const float4* gv4 = (const float4*)(gv + (size_t)row0 * DDIM);
        float4* sv4 = (float4*)sv;
        #pragma unroll
        for (int i = 0; i < 8; ++i) sv4[tid + i * THREADS] = gv4[tid + i * THREADS];
        #pragma unroll
        for (int i = 0; i < 8; ++i) {
            int idx = tid + i * THREADS;
            sWU[(idx >> 6) * WUS + (idx & 63)] = g_WU[idx];
        }
    }
    __syncthreads();

    const int steps = gsteps ? gsteps[0] : 4;

    // ---- prologue: h0 = v@U, fU = force@U (2 rows/warp, 2 kout/lane) ----
    {
        float ah00=0.f, ah01=0.f, ah10=0.f, ah11=0.f;
        float af00=0.f, af01=0.f, af10=0.f, af11=0.f;
        const int pr0 = 2 * wid, pr1 = 2 * wid + 1;
        #pragma unroll 1
        for (int c = 0; c < 4; ++c) {
            if (c < 3) { CP_WAIT1(); } else { CP_WAIT0(); }
            __syncthreads();
            const float* sU = stage + (c & 1) * 8192;
            const float* p0 = sv + pr0 * DDIM + c * 128;
            const float* p1 = sv + pr1 * DDIM + c * 128;
            const float* q0 = gf + (size_t)(row0 + pr0) * DDIM + c * 128;
            const float* q1 = gf + (size_t)(row0 + pr1) * DDIM + c * 128;
            const float* ub = sU + 2 * lane;
            #pragma unroll 4
            for (int d4 = 0; d4 < 32; ++d4) {
                float4 v0 = *(const float4*)(p0 + d4 * 4);
                float4 v1 = *(const float4*)(p1 + d4 * 4);
                float4 f0 = *(const float4*)(q0 + d4 * 4);
                float4 f1 = *(const float4*)(q1 + d4 * 4);
                const float* u = ub + (d4 * 4) * KDIM;
                float2 t;
                t = *(const float2*)(u);
                ah00 = fmaf(v0.x, t.x, ah00); ah01 = fmaf(v0.x, t.y, ah01);
                ah10 = fmaf(v1.x, t.x, ah10); ah11 = fmaf(v1.x, t.y, ah11);
                af00 = fmaf(f0.x, t.x, af00); af01 = fmaf(f0.x, t.y, af01);
                af10 = fmaf(f1.x, t.x, af10); af11 = fmaf(f1.x, t.y, af11);
                t = *(const float2*)(u + KDIM);
                ah00 = fmaf(v0.y, t.x, ah00); ah01 = fmaf(v0.y, t.y, ah01);
                ah10 = fmaf(v1.y, t.x, ah10); ah11 = fmaf(v1.y, t.y, ah11);
                af00 = fmaf(f0.y, t.x, af00); af01 = fmaf(f0.y, t.y, af01);
                af10 = fmaf(f1.y, t.x, af10); af11 = fmaf(f1.y, t.y, af11);
                t = *(const float2*)(u + 2 * KDIM);
                ah00 = fmaf(v0.z, t.x, ah00); ah01 = fmaf(v0.z, t.y, ah01);
                ah10 = fmaf(v1.z, t.x, ah10); ah11 = fmaf(v1.z, t.y, ah11);
                af00 = fmaf(f0.z, t.x, af00); af01 = fmaf(f0.z, t.y, af01);
                af10 = fmaf(f1.z, t.x, af10); af11 = fmaf(f1.z, t.y, af11);
                t = *(const float2*)(u + 3 * KDIM);
                ah00 = fmaf(v0.w, t.x, ah00); ah01 = fmaf(v0.w, t.y, ah01);
                ah10 = fmaf(v1.w, t.x, ah10); ah11 = fmaf(v1.w, t.y, ah11);
                af00 = fmaf(f0.w, t.x, af00); af01 = fmaf(f0.w, t.y, af01);
                af10 = fmaf(f1.w, t.x, af10); af11 = fmaf(f1.w, t.y, af11);
            }
            __syncthreads();
            if (c < 2) issueU(c + 2);
        }
        sh[pr0 * KDIM + 2 * lane] = ah00;  sh[pr0 * KDIM + 2 * lane + 1] = ah01;
        sh[pr1 * KDIM + 2 * lane] = ah10;  sh[pr1 * KDIM + 2 * lane + 1] = ah11;
        sfU[pr0 * KDIM + 2 * lane] = af00; sfU[pr0 * KDIM + 2 * lane + 1] = af01;
        sfU[pr1 * KDIM + 2 * lane] = af10; sfU[pr1 * KDIM + 2 * lane + 1] = af11;
    }
    issueW(0); issueW(1);   // epilogue W prefetch rides through all evals
    __syncthreads();

    // per-thread K-space state
    float4 h  = *(const float4*)(sh  + er * KDIM + ec);
    float4 fU = *(const float4*)(sfU + er * KDIM + ec);
    float4 Sv = make_float4(0.f, 0.f, 0.f, 0.f);
    float4 Sx = make_float4(0.f, 0.f, 0.f, 0.f);

    const double TH  = 1.0 / (2.0 - cbrt(2.0));
    const float d1dtF = (float)(TH * 0.01);
    const float d2dtF = (float)((1.0 - 2.0 * TH) * 0.01);
    const float wv1 = (float)TH;
    const float wv2 = (float)(1.0 - 2.0 * TH);
    double Gam = 0.0;
    for (int s = 0; s < steps; ++s) {
        double R = (double)(steps - 1 - s);
        Gam += TH * (1.0 - 0.5 * TH + R) + (1.0 - 2.0 * TH) * (0.5 + R) + TH * (0.5 * TH + R);
    }

    int p = 0;
    auto evalstep = [&](float ddt, float wv, float wx) {
        float* h2b = kbuf + p * 2176;
        float4 h2;
        h2.x = __fmul_rn(h.x, h.x); h2.y = __fmul_rn(h.y, h.y);
        h2.z = __fmul_rn(h.z, h.z); h2.w = __fmul_rn(h.w, h.w);
        *(float4*)(h2b + er * H2SS + ec) = h2;
        __syncthreads();
        float4 out = make_float4(0.f, 0.f, 0.f, 0.f);
        const float* hr = h2b + er * H2SS;
        const float* wc = sWU + ec;
        #pragma unroll 8
        for (int kin = 0; kin < KDIM; ++kin) {
            float hv = hr[kin];
            float4 wu = *(const float4*)(wc + kin * WUS);
            out.x = fmaf(hv, wu.x, out.x);
            out.y = fmaf(hv, wu.y, out.y);
            out.z = fmaf(hv, wu.z, out.z);
            out.w = fmaf(hv, wu.w, out.w);
        }
        Sv.x = fmaf(wv, h2.x, Sv.x); Sv.y = fmaf(wv, h2.y, Sv.y);
        Sv.z = fmaf(wv, h2.z, Sv.z); Sv.w = fmaf(wv, h2.w, Sv.w);
        Sx.x = fmaf(wx, h2.x, Sx.x); Sx.y = fmaf(wx, h2.y, Sx.y);
        Sx.z = fmaf(wx, h2.z, Sx.z); Sx.w = fmaf(wx, h2.w, Sx.w);
        h.x = __fadd_rn(h.x, __fmul_rn(ddt, __fadd_rn(-out.x, fU.x)));
        h.y = __fadd_rn(h.y, __fmul_rn(ddt, __fadd_rn(-out.y, fU.y)));
        h.z = __fadd_rn(h.z, __fmul_rn(ddt, __fadd_rn(-out.z, fU.z)));
        h.w = __fadd_rn(h.w, __fmul_rn(ddt, __fadd_rn(-out.w, fU.w)));
        p ^= 1;
    };

    for (int s = 0; s < steps; ++s) {
        double R = (double)(steps - 1 - s);
        float wx1 = (float)(TH * (1.0 - 0.5 * TH + R));
        float wx2 = (float)((1.0 - 2.0 * TH) * (0.5 + R));
        float wx3 = (float)(TH * (0.5 * TH + R));
        evalstep(d1dtF, wv1, wx1);
        evalstep(d2dtF, wv2, wx2);
        evalstep(d1dtF, wv1, wx3);
    }

    // ---- epilogue ----
    __syncthreads();                     // all mini reads of kbuf done
    float* stv = kbuf;                   // [64][STS_] transposed S_v
    float* stx = kbuf + KDIM * STS_;     // [64][STS_] transposed S_x
    stv[(ec + 0) * STS_ + er] = Sv.x; stv[(ec + 1) * STS_ + er] = Sv.y;
    stv[(ec + 2) * STS_ + er] = Sv.z; stv[(ec + 3) * STS_ + er] = Sv.w;
    stx[(ec + 0) * STS_ + er] = Sx.x; stx[(ec + 1) * STS_ + er] = Sx.y;
    stx[(ec + 2) * STS_ + er] = Sx.z; stx[(ec + 3) * STS_ + er] = Sx.w;

    const float dtF      = 0.01f;
    const float dt2F     = 1e-4f;
    const float stepsF   = (float)steps;
    const float stepsdtF = (float)((double)steps * 0.01);
    const float GamF     = (float)Gam;

    #pragma unroll 1
    for (int P = 0; P < 2; ++P) {
        CP_WAIT0(); __syncthreads();
        const float* sWc = stage + cc * 8192;        // chunk 2P+cc
        float4 Av[8], Ax[8];
        #pragma unroll
        for (int i = 0; i < 8; ++i) { Av[i] = make_float4(0.f,0.f,0.f,0.f); Ax[i] = make_float4(0.f,0.f,0.f,0.f); }
        const float* wb = sWc + lane * 4 + ks * 32 * 128;
        const float* bv = stv + 8 * g + ks * 32 * STS_;
        const float* bx = stx + 8 * g + ks * 32 * STS_;
        #pragma unroll 4
        for (int k = 0; k < 32; ++k) {
            float4 wv = *(const float4*)(wb + k * 128);
            float4 a0 = *(const float4*)(bv + k * STS_);
            float4 a1 = *(const float4*)(bv + k * STS_ + 4);
            float4 c0 = *(const float4*)(bx + k * STS_);
            float4 c1 = *(const float4*)(bx + k * STS_ + 4);
            Av[0].x = fmaf(a0.x, wv.x, Av[0].x); Av[0].y = fmaf(a0.x, wv.y, Av[0].y);
            Av[0].z = fmaf(a0.x, wv.z, Av[0].z); Av[0].w = fmaf(a0.x, wv.w, Av[0].w);
            Av[1].x = fmaf(a0.y, wv.x, Av[1].x); Av[1].y = fmaf(a0.y, wv.y, Av[1].y);
            Av[1].z = fmaf(a0.y, wv.z, Av[1].z); Av[1].w = fmaf(a0.y, wv.w, Av[1].w);
            Av[2].x = fmaf(a0.z, wv.x, Av[2].x); Av[2].y = fmaf(a0.z, wv.y, Av[2].y);
            Av[2].z = fmaf(a0.z, wv.z, Av[2].z); Av[2].w = fmaf(a0.z, wv.w, Av[2].w);
            Av[3].x = fmaf(a0.w, wv.x, Av[3].x); Av[3].y = fmaf(a0.w, wv.y, Av[3].y);
            Av[3].z = fmaf(a0.w, wv.z, Av[3].z); Av[3].w = fmaf(a0.w, wv.w, Av[3].w);
            Av[4].x = fmaf(a1.x, wv.x, Av[4].x); Av[4].y = fmaf(a1.x, wv.y, Av[4].y);
            Av[4].z = fmaf(a1.x, wv.z, Av[4].z); Av[4].w = fmaf(a1.x, wv.w, Av[4].w);
            Av[5].x = fmaf(a1.y, wv.x, Av[5].x); Av[5].y = fmaf(a1.y, wv.y, Av[5].y);
            Av[5].z = fmaf(a1.y, wv.z, Av[5].z); Av[5].w = fmaf(a1.y, wv.w, Av[5].w);
            Av[6].x = fmaf(a1.z, wv.x, Av[6].x); Av[6].y = fmaf(a1.z, wv.y, Av[6].y);
            Av[6].z = fmaf(a1.z, wv.z, Av[6].z); Av[6].w = fmaf(a1.z, wv.w, Av[6].w);
            Av[7].x = fmaf(a1.w, wv.x, Av[7].x); Av[7].y = fmaf(a1.w, wv.y, Av[7].y);
            Av[7].z = fmaf(a1.w, wv.z, Av[7].z); Av[7].w = fmaf(a1.w, wv.w, Av[7].w);
            Ax[0].x = fmaf(c0.x, wv.x, Ax[0].x); Ax[0].y = fmaf(c0.x, wv.y, Ax[0].y);
            Ax[0].z = fmaf(c0.x, wv.z, Ax[0].z); Ax[0].w = fmaf(c0.x, wv.w, Ax[0].w);
            Ax[1].x = fmaf(c0.y, wv.x, Ax[1].x); Ax[1].y = fmaf(c0.y, wv.y, Ax[1].y);
            Ax[1].z = fmaf(c0.y, wv.z, Ax[1].z); Ax[1].w = fmaf(c0.y, wv.w, Ax[1].w);
            Ax[2].x = fmaf(c0.z, wv.x, Ax[2].x); Ax[2].y = fmaf(c0.z, wv.y, Ax[2].y);
            Ax[2].z = fmaf(c0.z, wv.z, Ax[2].z); Ax[2].w = fmaf(c0.z, wv.w, Ax[2].w);
            Ax[3].x = fmaf(c0.w, wv.x, Ax[3].x); Ax[3].y = fmaf(c0.w, wv.y, Ax[3].y);
            Ax[3].z = fmaf(c0.w, wv.z, Ax[3].z); Ax[3].w = fmaf(c0.w, wv.w, Ax[3].w);
            Ax[4].x = fmaf(c1.x, wv.x, Ax[4].x); Ax[4].y = fmaf(c1.x, wv.y, Ax[4].y);
            Ax[4].z = fmaf(c1.x, wv.z, Ax[4].z); Ax[4].w = fmaf(c1.x, wv.w, Ax[4].w);
            Ax[5].x = fmaf(c1.y, wv.x, Ax[5].x); Ax[5].y = fmaf(c1.y, wv.y, Ax[5].y);
            Ax[5].z = fmaf(c1.y, wv.z, Ax[5].z); Ax[5].w = fmaf(c1.y, wv.w, Ax[5].w);
            Ax[6].x = fmaf(c1.z, wv.x, Ax[6].x); Ax[6].y = fmaf(c1.z, wv.y, Ax[6].y);
            Ax[6].z = fmaf(c1.z, wv.z, Ax[6].z); Ax[6].w = fmaf(c1.z, wv.w, Ax[6].w);
            Ax[7].x = fmaf(c1.w, wv.x, Ax[7].x); Ax[7].y = fmaf(c1.w, wv.y, Ax[7].y);
            Ax[7].z = fmaf(c1.w, wv.z, Ax[7].z); Ax[7].w = fmaf(c1.w, wv.w, Ax[7].w);
        }
        __syncthreads();
        if (P == 0) { issueW(2); issueW(3); }

        const int chunk = 2 * P + cc;
        const int col = chunk * 128 + lane * 4;
        float* sp = spart + (g * 2 + cc) * 1024 + lane * 4;

        if (ks == 1) {
            #pragma unroll
            for (int i = 0; i < 8; ++i) *(float4*)(sp + i * 128) = Av[i];
        }
        __syncthreads();
        if (ks == 0) {                               // merge Gv, emit v
            #pragma unroll
            for (int i = 0; i < 8; ++i) {
                const int r = 8 * g + i;
                float4 q = *(const float4*)(sp + i * 128);
                float gvx = __fadd_rn(Av[i].x, q.x), gvy = __fadd_rn(Av[i].y, q.y);
                float gvz = __fadd_rn(Av[i].z, q.z), gvw = __fadd_rn(Av[i].w, q.w);
                float4 fv = *(const float4*)(gf + (size_t)(row0 + r) * DDIM + col);
                float4 v0 = *(const float4*)(sv + r * DDIM + col);
                float4 vo;
                vo.x = __fadd_rn(v0.x, __fmul_rn(dtF, __fadd_rn(-gvx, __fmul_rn(stepsF, fv.x))));
                vo.y = __fadd_rn(v0.y, __fmul_rn(dtF, __fadd_rn(-gvy, __fmul_rn(stepsF, fv.y))));
                vo.z = __fadd_rn(v0.z, __fmul_rn(dtF, __fadd_rn(-gvz, __fmul_rn(stepsF, fv.z))));
                vo.w = __fadd_rn(v0.w, __fmul_rn(dtF, __fadd_rn(-gvw, __fmul_rn(stepsF, fv.w))));
                *(float4*)(gov + (size_t)(row0 + r) * DDIM + col) = vo;
            }
        }
        __syncthreads();
        if (ks == 1) {
            #pragma unroll
            for (int i = 0; i < 8; ++i) *(float4*)(sp + i * 128) = Ax[i];
        }
        __syncthreads();
        if (ks == 0) {                               // merge Gx, emit x
            #pragma unroll
            for (int i = 0; i < 8; ++i) {
                const int r = 8 * g + i;
                float4 q = *(const float4*)(sp + i * 128);
                float gxx = __fadd_rn(Ax[i].x, q.x), gxy = __fadd_rn(Ax[i].y, q.y);
                float gxz = __fadd_rn(Ax[i].z, q.z), gxw = __fadd_rn(Ax[i].w, q.w);
                float4 fv = *(const float4*)(gf + (size_t)(row0 + r) * DDIM + col);
                float4 x0 = *(const float4*)(gx + (size_t)(row0 + r) * DDIM + col);
                float4 v0 = *(const float4*)(sv + r * DDIM + col);
                float4 xo;
                xo.x = __fadd_rn(fmaf(stepsdtF, v0.x, x0.x),
                                 __fmul_rn(dt2F, __fadd_rn(-gxx, __fmul_rn(GamF, fv.x))));
                xo.y = __fadd_rn(fmaf(stepsdtF, v0.y, x0.y),
                                 __fmul_rn(dt2F, __fadd_rn(-gxy, __fmul_rn(GamF, fv.y))));
                xo.z = __fadd_rn(fmaf(stepsdtF, v0.z, x0.z),
                                 __fmul_rn(dt2F, __fadd_rn(-gxz, __fmul_rn(GamF, fv.z))));
                xo.w = __fadd_rn(fmaf(stepsdtF, v0.w, x0.w),
                                 __fmul_rn(dt2F, __fadd_rn(-gxw, __fmul_rn(GamF, fv.w))));
                if (steps != 0) {                    // steps==0 reference never wraps
                    xo.x = wrap_torus(xo.x); xo.y = wrap_torus(xo.y);
                    xo.z = wrap_torus(xo.z); xo.w = wrap_torus(xo.w);
                }
                *(float4*)(gox + (size_t)(row0 + r) * DDIM + col) = xo;
            }
        }
    }
    CP_WAIT0();
}

extern "C" void kernel_launch(void* const* d_in, const int* in_sizes, int n_in,
                              void* d_out, int out_size)
{
    const float* x = (const float*)d_in[0];
    const float* v = (const float*)d_in[1];
    const float* f = (const float*)d_in[2];
    const float* U = (const float*)d_in[3];
    const float* W = (const float*)d_in[4];
    const int* steps = (n_in >= 6) ? (const int*)d_in[5] : nullptr;

    const int B  = in_sizes[0] / DDIM;
    const int BD = B * DDIM;
    float* ox = (float*)d_out;
    float* ov = ox + BD;

    wu_kernel<<<16, 256>>>(W, U);

    const int smem_floats = 16384 + 2048 + 2048 + 4608 + 4352 + 8192 + 16384;  // 54016
    const int smem_bytes = smem_floats * 4;                                    // 216064
    cudaFuncSetAttribute(fr_kernel, cudaFuncAttributeMaxDynamicSharedMemorySize, smem_bytes);
    fr_kernel<<<B / CTA_M, THREADS, smem_bytes>>>(x, v, f, U, W, steps, ox, ov);
}